// round 5
// baseline (speedup 1.0000x reference)
#include <cuda_runtime.h>
#include <math.h>
#include <stdint.h>

#define TT 512
#define BB 64
#define DD 1024
#define HH 1024
#define GG 4096   // 4*H
#define NCTA 128

// Scratch (allocation-free rules: __device__ globals)
static __device__ float g_gx[(size_t)TT * BB * GG];   // precomputed input gates (+ both biases)
static __device__ unsigned g_arrive = 0;
static __device__ unsigned g_release = 0;

// Packed fp32x2 helpers (sm_103a FFMA2 — 2 exact fp32 FMAs per issue)
#define FFMA2(acc, a, b) \
    asm("fma.rn.f32x2 %0, %1, %2, %0;" : "+l"(acc) : "l"(a), "l"(b))
#define DUP2(dst, s) \
    asm("mov.b64 %0, {%1, %1};" : "=l"(dst) : "f"(s))
#define UNPK2(lo, hi, src) \
    asm("mov.b64 {%0, %1}, %2;" : "=f"(lo), "=f"(hi) : "l"(src))

// ---------------------------------------------------------------------------
// Phase 1: gates_x[t*B+b, n] = sum_k x[t,b,k]*w_ih[n,k] + b_ih[n] + b_hh[n]
// 128x128x16 fp32 SGEMM, NT layout, FFMA2 inner product.
// ---------------------------------------------------------------------------
__global__ __launch_bounds__(256) void gemm_gx_kernel(
    const float* __restrict__ X,     // [32768, 1024]
    const float* __restrict__ W,     // [4096, 1024]
    const float* __restrict__ bih,
    const float* __restrict__ bhh)
{
    __shared__ __align__(16) float As[16][128];
    __shared__ __align__(16) float Bs[16][128];
    const int bm = blockIdx.y * 128;
    const int bn = blockIdx.x * 128;
    const int tid = threadIdx.x;
    const int trow = (tid >> 4) << 3;
    const int tcol = (tid & 15) << 3;

    // accp[p][j]: rows (trow+2p, trow+2p+1), col (tcol+j), packed fp32x2
    uint64_t accp[4][8];
#pragma unroll
    for (int p = 0; p < 4; p++)
#pragma unroll
        for (int j = 0; j < 8; j++) accp[p][j] = 0ull;

    for (int k0 = 0; k0 < DD; k0 += 16) {
#pragma unroll
        for (int i = 0; i < 2; i++) {
            int idx = tid + (i << 8);
            int row = idx >> 2;
            int kv  = (idx & 3) << 2;
            float4 a = *(const float4*)(X + (size_t)(bm + row) * DD + k0 + kv);
            As[kv + 0][row] = a.x; As[kv + 1][row] = a.y;
            As[kv + 2][row] = a.z; As[kv + 3][row] = a.w;
            float4 b = *(const float4*)(W + (size_t)(bn + row) * DD + k0 + kv);
            Bs[kv + 0][row] = b.x; Bs[kv + 1][row] = b.y;
            Bs[kv + 2][row] = b.z; Bs[kv + 3][row] = b.w;
        }
        __syncthreads();
#pragma unroll
        for (int k = 0; k < 16; k++) {
            // a rows as packed pairs (free: contiguous in As)
            ulonglong2 a01 = *(const ulonglong2*)&As[k][trow];
            ulonglong2 a23 = *(const ulonglong2*)&As[k][trow + 4];
            uint64_t ap[4] = {a01.x, a01.y, a23.x, a23.y};
            float4 b0 = *(const float4*)&Bs[k][tcol];
            float4 b1 = *(const float4*)&Bs[k][tcol + 4];
            uint64_t bd[8];
            DUP2(bd[0], b0.x); DUP2(bd[1], b0.y);
            DUP2(bd[2], b0.z); DUP2(bd[3], b0.w);
            DUP2(bd[4], b1.x); DUP2(bd[5], b1.y);
            DUP2(bd[6], b1.z); DUP2(bd[7], b1.w);
#pragma unroll
            for (int p = 0; p < 4; p++)
#pragma unroll
                for (int j = 0; j < 8; j++)
                    FFMA2(accp[p][j], ap[p], bd[j]);
        }
        __syncthreads();
    }

#pragma unroll
    for (int p = 0; p < 4; p++) {
#pragma unroll
        for (int j = 0; j < 8; j++) {
            float lo, hi;
            UNPK2(lo, hi, accp[p][j]);
            int n = bn + tcol + j;
            size_t m0 = (size_t)(bm + trow + 2 * p);
            g_gx[m0 * GG + n]        = lo + bih[n] + bhh[n];
            g_gx[(m0 + 1) * GG + n]  = hi + bih[n] + bhh[n];
        }
    }
}

// ---------------------------------------------------------------------------
// Phase 2: persistent recurrence kernel. 128 CTAs (1/SM), 256 threads.
// CTA owns h-columns j0..j0+7 across all 4 gates (32 gathered w_hh rows) in
// SMEM for the whole kernel. Cell state c in registers. Grid barrier per step.
// Inner product uses FFMA2 with row-pair packed h (free from LDS.128).
// ---------------------------------------------------------------------------
__global__ __launch_bounds__(256, 1) void lstm_persist_kernel(
    const float* __restrict__ W,    // w_hh [4096, 1024]
    const float* __restrict__ h0,
    const float* __restrict__ c0,
    float* __restrict__ out)
{
    extern __shared__ float smem[];
    float* Ws = smem;                 // [1024][32], col swizzled by (k&28)
    float* Hsb = smem + 1024 * 32;    // [2][64][64], col swizzled by (k&28)

    const int tid = threadIdx.x;
    const int tx  = tid & 15;         // out col pair 2tx,2tx+1
    const int ty  = tid >> 4;         // out rows 4ty..4ty+3
    const int j0  = blockIdx.x * 8;

    const unsigned rel_base = *(volatile unsigned*)&g_release;

    // ---- Load W slice into SMEM (once) ----
#pragma unroll 4
    for (int r = 0; r < 32; r++) {
        int idx = r * 256 + tid;
        int k4  = idx & 255;
        int c   = idx >> 8;
        int k   = k4 << 2;
        int row = (c >> 3) * HH + j0 + (c & 7);
        float4 v = *(const float4*)(W + (size_t)row * HH + k);
        int col = c ^ (k & 28);
        Ws[(k + 0) * 32 + col] = v.x;
        Ws[(k + 1) * 32 + col] = v.y;
        Ws[(k + 2) * 32 + col] = v.z;
        Ws[(k + 3) * 32 + col] = v.w;
    }

    // ---- Cell state in registers ----
    float c_reg[2];
#pragma unroll
    for (int i = 0; i < 2; i++) {
        int idx = tid + (i << 8);
        int b = idx >> 3, jl = idx & 7;
        c_reg[i] = c0[(size_t)b * HH + j0 + jl];
    }
    __syncthreads();

    const int hkv = tx << 2;          // local k offset 0..60

    for (int t = 0; t < TT; t++) {
        const float* __restrict__ h_in =
            (t == 0) ? h0 : out + (size_t)(t - 1) * BB * HH;
        const float* __restrict__ gx = g_gx + (size_t)t * BB * GG;

        // Prefetch gx (hidden under FMA work)
        float gpre[2][4];
#pragma unroll
        for (int i = 0; i < 2; i++) {
            int idx = tid + (i << 8);
            int b = idx >> 3, jl = idx & 7;
            const float* gr = gx + (size_t)b * GG + j0 + jl;
#pragma unroll
            for (int g = 0; g < 4; g++) gpre[i][g] = gr[g * HH];
        }

        // accp[p][j]: rows (4ty+2p, 4ty+2p+1), col (2tx+j), packed fp32x2
        uint64_t acc00 = 0ull, acc01 = 0ull, acc10 = 0ull, acc11 = 0ull;

        // Preload tile 0
        {
            const float* hsrc = h_in + hkv;
#pragma unroll
            for (int r = 0; r < 4; r++) {
                float4 v = *(const float4*)(hsrc + (size_t)(ty + 16 * r) * HH);
                int col = (ty + 16 * r) ^ (hkv & 28);
                float* dst = Hsb + (hkv * 64) + col;
                dst[0]   = v.x; dst[64]  = v.y;
                dst[128] = v.z; dst[192] = v.w;
            }
        }
        __syncthreads();

        for (int it = 0; it < 16; ++it) {
            float4 pre[4];
            if (it < 15) {
                const float* hsrc = h_in + (it + 1) * 64 + hkv;
#pragma unroll
                for (int r = 0; r < 4; r++)
                    pre[r] = *(const float4*)(hsrc + (size_t)(ty + 16 * r) * HH);
            }
            const float* cur = Hsb + (it & 1) * 4096;
            const float* WsK = Ws + (it * 64) * 32;
#pragma unroll
            for (int kk = 0; kk < 64; kk++) {
                int kq = kk & 28;
                float2 w2 = *(const float2*)(WsK + kk * 32 + ((2 * tx) ^ kq));
                ulonglong2 hp = *(const ulonglong2*)(cur + kk * 64 + ((4 * ty) ^ kq));
                uint64_t wxx, wyy;
                DUP2(wxx, w2.x);
                DUP2(wyy, w2.y);
                FFMA2(acc00, hp.x, wxx);
                FFMA2(acc01, hp.x, wyy);
                FFMA2(acc10, hp.y, wxx);
                FFMA2(acc11, hp.y, wyy);
            }
            __syncthreads();
            if (it < 15) {
                float* nxt = Hsb + ((it + 1) & 1) * 4096;
#pragma unroll
                for (int r = 0; r < 4; r++) {
                    int col = (ty + 16 * r) ^ (hkv & 28);
                    float* dst = nxt + hkv * 64 + col;
                    dst[0]   = pre[r].x; dst[64]  = pre[r].y;
                    dst[128] = pre[r].z; dst[192] = pre[r].w;
                }
                __syncthreads();
            }
        }

        // Unpack accumulators: acc[r][j] with rows 4ty+r
        float accf[4][2];
        UNPK2(accf[0][0], accf[1][0], acc00);
        UNPK2(accf[0][1], accf[1][1], acc01);
        UNPK2(accf[2][0], accf[3][0], acc10);
        UNPK2(accf[2][1], accf[3][1], acc11);

        // Stage matmul results to smem (stride 33)
        float* sg = Hsb;
#pragma unroll
        for (int r = 0; r < 4; r++) {
#pragma unroll
            for (int jj = 0; jj < 2; jj++)
                sg[(4 * ty + r) * 33 + (2 * tx + jj)] = accf[r][jj];
        }
        __syncthreads();

        // Pointwise LSTM cell
        float* h_out = out + (size_t)t * BB * HH;
#pragma unroll
        for (int i = 0; i < 2; i++) {
            int idx = tid + (i << 8);
            int b = idx >> 3, jl = idx & 7;
            float gi = sg[b * 33 + jl]      + gpre[i][0];
            float gf = sg[b * 33 + 8 + jl]  + gpre[i][1];
            float gg = sg[b * 33 + 16 + jl] + gpre[i][2];
            float go = sg[b * 33 + 24 + jl] + gpre[i][3];
            float ig = 1.0f / (1.0f + __expf(-gi));
            float fg = 1.0f / (1.0f + __expf(-gf));
            float gv = tanhf(gg);
            float og = 1.0f / (1.0f + __expf(-go));
            float cn = fg * c_reg[i] + ig * gv;
            float hn = og * tanhf(cn);
            c_reg[i] = cn;
            h_out[(size_t)b * HH + j0 + jl] = hn;
            if (t == TT - 1) {
                out[(size_t)TT * BB * HH + (size_t)b * HH + j0 + jl] = hn;
                out[(size_t)TT * BB * HH + BB * HH + (size_t)b * HH + j0 + jl] = cn;
            }
        }

        // Grid-wide barrier
        if (t < TT - 1) {
            __threadfence();
            __syncthreads();
            if (tid == 0) {
                unsigned target = rel_base + (unsigned)(t + 1);
                unsigned old = atomicAdd(&g_arrive, 1);
                if (old == NCTA - 1) {
                    g_arrive = 0;
                    __threadfence();
                    *(volatile unsigned*)&g_release = target;
                } else {
                    while ((int)(*(volatile unsigned*)&g_release - target) < 0) {}
                    __threadfence();
                }
            }
            __syncthreads();
        }
    }
}

extern "C" void kernel_launch(void* const* d_in, const int* in_sizes, int n_in,
                              void* d_out, int out_size)
{
    const float* x    = (const float*)d_in[0];
    const float* h0   = (const float*)d_in[1];
    const float* c0   = (const float*)d_in[2];
    const float* w_ih = (const float*)d_in[3];
    const float* b_ih = (const float*)d_in[4];
    const float* w_hh = (const float*)d_in[5];
    const float* b_hh = (const float*)d_in[6];
    float* out = (float*)d_out;

    (void)in_sizes; (void)n_in; (void)out_size;

    // Phase 1: big input-projection GEMM (biases folded)
    dim3 g1(GG / 128, (TT * BB) / 128);
    gemm_gx_kernel<<<g1, 256>>>(x, w_ih, b_ih, b_hh);

    // Phase 2: persistent recurrence (whole scan in one kernel)
    const int smem_bytes = (1024 * 32 + 2 * 64 * 64) * (int)sizeof(float); // 160 KB
    cudaFuncSetAttribute(lstm_persist_kernel,
                         cudaFuncAttributeMaxDynamicSharedMemorySize, smem_bytes);
    lstm_persist_kernel<<<NCTA, 256, smem_bytes>>>(w_hh, h0, c0, out);
}

// round 7
// speedup vs baseline: 2.1504x; 2.1504x over previous
#include <cuda_runtime.h>
#include <cuda_bf16.h>
#include <math.h>
#include <stdint.h>

#define TT 512
#define BB 64
#define DD 1024
#define HH 1024
#define GG 4096
#define NCTA 128

// ---------------------------------------------------------------------------
// Device scratch (allocation-free rules: __device__ globals)
// ---------------------------------------------------------------------------
static __device__ float g_gx[(size_t)TT * BB * GG];            // input gates (+biases)
static __device__ __nv_bfloat16 g_xhi[(size_t)TT * BB * DD];   // x split
static __device__ __nv_bfloat16 g_xlo[(size_t)TT * BB * DD];
static __device__ __nv_bfloat16 g_wihhi[GG * DD];              // w_ih split
static __device__ __nv_bfloat16 g_wihlo[GG * DD];
static __device__ __nv_bfloat16 g_whhhi[GG * HH];              // w_hh split, CTA-tiled rows
static __device__ __nv_bfloat16 g_whhlo[GG * HH];
static __device__ __nv_bfloat16 g_hhi[2][BB * HH];             // h split ping-pong
static __device__ __nv_bfloat16 g_hlo[2][BB * HH];
static __device__ unsigned g_arrive = 0;
static __device__ unsigned g_release = 0;

// ---------------------------------------------------------------------------
// Baseline-PTX tensor helpers (sm_80+: compile for plain sm_103)
// ---------------------------------------------------------------------------
__device__ __forceinline__ uint32_t smem_u32(const void* p) {
    uint32_t a;
    asm("{ .reg .u64 t; cvta.to.shared.u64 t, %1; cvt.u32.u64 %0, t; }"
        : "=r"(a) : "l"(p));
    return a;
}
__device__ __forceinline__ void cp16(uint32_t dst, const void* src) {
    asm volatile("cp.async.cg.shared.global [%0], [%1], 16;" :: "r"(dst), "l"(src) : "memory");
}
#define CP_COMMIT() asm volatile("cp.async.commit_group;" ::: "memory")
#define CP_WAIT0()  asm volatile("cp.async.wait_group 0;" ::: "memory")
#define CP_WAIT1()  asm volatile("cp.async.wait_group 1;" ::: "memory")

__device__ __forceinline__ void ldsm4(uint32_t addr, uint32_t* r) {
    asm volatile("ldmatrix.sync.aligned.m8n8.x4.shared.b16 {%0,%1,%2,%3}, [%4];"
                 : "=r"(r[0]), "=r"(r[1]), "=r"(r[2]), "=r"(r[3]) : "r"(addr));
}
__device__ __forceinline__ void mma16816(float* c, const uint32_t* a, const uint32_t* b) {
    asm volatile("mma.sync.aligned.m16n8k16.row.col.f32.bf16.bf16.f32 "
                 "{%0,%1,%2,%3}, {%4,%5,%6,%7}, {%8,%9}, {%0,%1,%2,%3};"
                 : "+f"(c[0]), "+f"(c[1]), "+f"(c[2]), "+f"(c[3])
                 : "r"(a[0]), "r"(a[1]), "r"(a[2]), "r"(a[3]), "r"(b[0]), "r"(b[1]));
}

// ---------------------------------------------------------------------------
// Prep kernels: fp32 -> bf16 hi/lo splits
// ---------------------------------------------------------------------------
__device__ __forceinline__ void split_bf16(float v, __nv_bfloat16* hi, __nv_bfloat16* lo) {
    __nv_bfloat16 h = __float2bfloat16(v);
    *hi = h;
    *lo = __float2bfloat16(v - __bfloat162float(h));
}
__global__ void prep_x_kernel(const float* __restrict__ x) {
    size_t idx = (size_t)blockIdx.x * blockDim.x + threadIdx.x;
    if (idx >= (size_t)TT * BB * DD) return;
    split_bf16(x[idx], &g_xhi[idx], &g_xlo[idx]);
}
__global__ void prep_wih_kernel(const float* __restrict__ w) {
    int idx = blockIdx.x * blockDim.x + threadIdx.x;
    if (idx >= GG * DD) return;
    split_bf16(w[idx], &g_wihhi[idx], &g_wihlo[idx]);
}
// w_hh reorder: CTA cta owns 32 rows r = g*8+jl  <->  in_row = g*1024 + cta*8 + jl
__global__ void prep_whh_kernel(const float* __restrict__ w) {
    int idx = blockIdx.x * blockDim.x + threadIdx.x;
    if (idx >= GG * HH) return;
    int orow = idx >> 10, k = idx & 1023;
    int cta = orow >> 5, r = orow & 31;
    int g = r >> 3, jl = r & 7;
    int in_row = (g << 10) + (cta << 3) + jl;
    split_bf16(w[(size_t)in_row * HH + k], &g_whhhi[idx], &g_whhlo[idx]);
}
__global__ void prep_h_kernel(const float* __restrict__ h0) {
    int idx = blockIdx.x * blockDim.x + threadIdx.x;
    if (idx >= BB * HH) return;
    split_bf16(h0[idx], &g_hhi[0][idx], &g_hlo[0][idx]);
}

// ---------------------------------------------------------------------------
// Phase 1: gates_x = x @ w_ih^T + b_ih + b_hh  via mma.sync, 3-term split.
// Tiles 128x128x32, cp.async double-buffered. Warp grid 4m x 2n (m32 x n64).
// SMEM row stride 40 bf16 (80B): conflict-free ldmatrix.
// ---------------------------------------------------------------------------
#define P1_STG 10240      // one stage of one array: 128*40*2
#define P1_AHI 0
#define P1_ALO 20480
#define P1_BHI 40960
#define P1_BLO 61440
#define P1_SMEM 81920

__global__ __launch_bounds__(256, 2) void gemm_gx_mma(
    const float* __restrict__ bih, const float* __restrict__ bhh)
{
    extern __shared__ __align__(16) char sm[];
    const uint32_t sb = smem_u32(sm);
    const int tid = threadIdx.x;
    const int wid = tid >> 5, l = tid & 31;
    const int bm = blockIdx.y * 128, bn = blockIdx.x * 128;
    const int wm = wid & 3, wn = wid >> 2;

    // ldmatrix per-lane geometry
    const int a_r = wm * 32 + (l & 7) + ((l >> 3) & 1) * 8;  // + am*16
    const int a_cb = ((l >> 4) & 1) * 8;
    const int b_r = wn * 64 + (l & 7) + ((l >> 4) & 1) * 8;  // + bg*16
    const int b_cb = ((l >> 3) & 1) * 8;

    float acc[2][8][4];
#pragma unroll
    for (int i = 0; i < 2; i++)
#pragma unroll
        for (int j = 0; j < 8; j++)
#pragma unroll
            for (int q = 0; q < 4; q++) acc[i][j][q] = 0.f;

    // stage loader
    const int crow = tid >> 2, cseg = tid & 3;  // covers 128 rows x 4 segs in 2 passes
    auto load_stage = [&](int c, int st) {
        const uint32_t so = st * P1_STG;
        size_t koff = (size_t)c * 32 + cseg * 8;
#pragma unroll
        for (int i = 0; i < 2; i++) {
            int row = crow + i * 64;
            uint32_t sofs = (uint32_t)(row * 80 + cseg * 16);
            cp16(sb + P1_AHI + so + sofs, g_xhi + (size_t)(bm + row) * DD + koff);
            cp16(sb + P1_ALO + so + sofs, g_xlo + (size_t)(bm + row) * DD + koff);
            cp16(sb + P1_BHI + so + sofs, g_wihhi + (size_t)(bn + row) * DD + koff);
            cp16(sb + P1_BLO + so + sofs, g_wihlo + (size_t)(bn + row) * DD + koff);
        }
        CP_COMMIT();
    };

    load_stage(0, 0);

    for (int c = 0; c < 32; c++) {
        if (c < 31) load_stage(c + 1, (c + 1) & 1);
        if (c < 31) { CP_WAIT1(); } else { CP_WAIT0(); }
        __syncthreads();
        const uint32_t so = (c & 1) * P1_STG;
#pragma unroll
        for (int kb = 0; kb < 32; kb += 16) {
            uint32_t ahi[2][4], alo[2][4];
#pragma unroll
            for (int am = 0; am < 2; am++) {
                uint32_t aofs = (uint32_t)((a_r + am * 16) * 80 + (kb + a_cb) * 2);
                ldsm4(sb + P1_AHI + so + aofs, ahi[am]);
                ldsm4(sb + P1_ALO + so + aofs, alo[am]);
            }
#pragma unroll
            for (int bg = 0; bg < 4; bg++) {
                uint32_t bh[4], bl[4];
                uint32_t bofs = (uint32_t)((b_r + bg * 16) * 80 + (kb + b_cb) * 2);
                ldsm4(sb + P1_BHI + so + bofs, bh);
                ldsm4(sb + P1_BLO + so + bofs, bl);
#pragma unroll
                for (int am = 0; am < 2; am++)
#pragma unroll
                    for (int na = 0; na < 2; na++) {
                        float* cc = acc[am][bg * 2 + na];
                        mma16816(cc, ahi[am], bh + na * 2);
                        mma16816(cc, alo[am], bh + na * 2);
                        mma16816(cc, ahi[am], bl + na * 2);
                    }
            }
        }
        __syncthreads();
    }

    // epilogue: add biases, write g_gx
#pragma unroll
    for (int am = 0; am < 2; am++) {
        int m0 = bm + wm * 32 + am * 16 + (l >> 2);
#pragma unroll
        for (int j = 0; j < 8; j++) {
            int n = bn + wn * 64 + j * 8 + 2 * (l & 3);
            float s0 = bih[n] + bhh[n];
            float s1 = bih[n + 1] + bhh[n + 1];
            float* c = acc[am][j];
            g_gx[(size_t)m0 * GG + n]           = c[0] + s0;
            g_gx[(size_t)m0 * GG + n + 1]       = c[1] + s1;
            g_gx[(size_t)(m0 + 8) * GG + n]     = c[2] + s0;
            g_gx[(size_t)(m0 + 8) * GG + n + 1] = c[3] + s1;
        }
    }
}

// ---------------------------------------------------------------------------
// Phase 2: persistent mma.sync recurrence. 128 CTAs x 256 threads.
// CTA: D[64 batch x 32 gate-rows], K=1024 (8 chunks of 128), 3-term split.
// W (hi+lo) resident in SMEM; h bf16 hi/lo streamed via cp.async ping-pong.
// Warp grid 4m x 2n (m16 x n16 per warp).
// ---------------------------------------------------------------------------
#define R_SWHI 0            // 32 x 2064B = 66048
#define R_SWLO 66048
#define R_SH   132096       // 2 stages x (hi 17408 + lo 17408)
#define R_HSTG 34816
#define R_SG   201728       // 64 x 36 floats = 9216
#define R_SMEM 210944

__global__ __launch_bounds__(256, 1) void lstm_mma_kernel(
    const float* __restrict__ c0, float* __restrict__ out)
{
    extern __shared__ __align__(16) char sm[];
    const uint32_t sb = smem_u32(sm);
    float* sg = (float*)(sm + R_SG);
    const int tid = threadIdx.x;
    const int wid = tid >> 5, l = tid & 31;
    const int j0 = blockIdx.x * 8;

    const unsigned rel_base = *(volatile unsigned*)&g_release;

    const __nv_bfloat16* whi = g_whhhi + (size_t)blockIdx.x * 32 * HH;
    const __nv_bfloat16* wlo = g_whhlo + (size_t)blockIdx.x * 32 * HH;

    // ---- Load W (hi+lo) into SMEM once: 32 rows x 1024 bf16 each ----
    for (int cid = tid; cid < 4096; cid += 256) {
        int row = cid >> 7, seg = cid & 127;
        uint32_t sofs = (uint32_t)(row * 2064 + seg * 16);
        *(uint4*)(sm + R_SWHI + sofs) = *(const uint4*)(whi + (size_t)row * HH + seg * 8);
        *(uint4*)(sm + R_SWLO + sofs) = *(const uint4*)(wlo + (size_t)row * HH + seg * 8);
    }

    // cell state: 2 elems/thread: e = tid + i*256 -> b = e>>3, jl = e&7
    float c_reg[2];
#pragma unroll
    for (int i = 0; i < 2; i++) {
        int e = tid + (i << 8);
        c_reg[i] = c0[(size_t)(e >> 3) * HH + j0 + (e & 7)];
    }
    __syncthreads();

    // per-lane ldmatrix geometry
    const int m0 = (wid & 3) * 16, n0 = (wid >> 2) * 16;
    const int a_r = m0 + (l & 7) + ((l >> 3) & 1) * 8;
    const int a_cb = ((l >> 4) & 1) * 8;
    const int b_r = n0 + (l & 7) + ((l >> 4) & 1) * 8;
    const int b_cb = ((l >> 3) & 1) * 8;

    const int hrow = tid >> 2, hseg4 = tid & 3;   // loader: 64 rows x 16 segs in 4 passes

    for (int t = 0; t < TT; t++) {
        const __nv_bfloat16* hhi = g_hhi[t & 1];
        const __nv_bfloat16* hlo = g_hlo[t & 1];
        const float* gx = g_gx + (size_t)t * BB * GG;

        // prefetch gx for pointwise (lands under MMA work)
        float gpre[2][4];
#pragma unroll
        for (int i = 0; i < 2; i++) {
            int e = tid + (i << 8);
            const float* gr = gx + (size_t)(e >> 3) * GG + j0 + (e & 7);
#pragma unroll
            for (int g = 0; g < 4; g++) gpre[i][g] = gr[g * HH];
        }

        float acc[2][4];
#pragma unroll
        for (int na = 0; na < 2; na++)
#pragma unroll
            for (int q = 0; q < 4; q++) acc[na][q] = 0.f;

        // stage loader: H chunk c into stage st
        auto load_h = [&](int c, int st) {
            const uint32_t so = R_SH + st * R_HSTG;
            const size_t base = (size_t)hrow * HH + c * 128;
#pragma unroll
            for (int i = 0; i < 4; i++) {
                int seg = hseg4 + i * 4;
                uint32_t sofs = (uint32_t)(hrow * 272 + seg * 16);
                cp16(sb + so + sofs,         hhi + base + seg * 8);
                cp16(sb + so + 17408 + sofs, hlo + base + seg * 8);
            }
            CP_COMMIT();
        };

        load_h(0, 0);
        for (int c = 0; c < 8; c++) {
            if (c < 7) load_h(c + 1, (c + 1) & 1);
            if (c < 7) { CP_WAIT1(); } else { CP_WAIT0(); }
            __syncthreads();
            const uint32_t so = R_SH + (c & 1) * R_HSTG;
#pragma unroll
            for (int kb = 0; kb < 128; kb += 16) {
                uint32_t ahi[4], alo[4], bh[4], bl[4];
                uint32_t aofs = (uint32_t)(a_r * 272 + (kb + a_cb) * 2);
                ldsm4(sb + so + aofs, ahi);
                ldsm4(sb + so + 17408 + aofs, alo);
                uint32_t bofs = (uint32_t)(b_r * 2064 + (c * 128 + kb + b_cb) * 2);
                ldsm4(sb + R_SWHI + bofs, bh);
                ldsm4(sb + R_SWLO + bofs, bl);
#pragma unroll
                for (int na = 0; na < 2; na++) {
                    mma16816(acc[na], ahi, bh + na * 2);
                    mma16816(acc[na], alo, bh + na * 2);
                    mma16816(acc[na], ahi, bl + na * 2);
                }
            }
            __syncthreads();
        }

        // stage D to SMEM: thread covers (m, n),(m,n+1),(m+8,*) per n-atom
        {
            int m = m0 + (l >> 2);
#pragma unroll
            for (int na = 0; na < 2; na++) {
                int n = n0 + na * 8 + 2 * (l & 3);
                *(float2*)&sg[m * 36 + n]       = make_float2(acc[na][0], acc[na][1]);
                *(float2*)&sg[(m + 8) * 36 + n] = make_float2(acc[na][2], acc[na][3]);
            }
        }
        __syncthreads();

        // pointwise LSTM cell: 512 elems, 2/thread
        float* h_out = out + (size_t)t * BB * HH;
        __nv_bfloat16* nhhi = g_hhi[(t + 1) & 1];
        __nv_bfloat16* nhlo = g_hlo[(t + 1) & 1];
#pragma unroll
        for (int i = 0; i < 2; i++) {
            int e = tid + (i << 8);
            int b = e >> 3, jl = e & 7;
            float gi = sg[b * 36 + jl]      + gpre[i][0];
            float gf = sg[b * 36 + 8 + jl]  + gpre[i][1];
            float gg = sg[b * 36 + 16 + jl] + gpre[i][2];
            float go = sg[b * 36 + 24 + jl] + gpre[i][3];
            float ig = 1.0f / (1.0f + __expf(-gi));
            float fg = 1.0f / (1.0f + __expf(-gf));
            float gv = tanhf(gg);
            float og = 1.0f / (1.0f + __expf(-go));
            float cn = fg * c_reg[i] + ig * gv;
            float hn = og * tanhf(cn);
            c_reg[i] = cn;
            size_t hoff = (size_t)b * HH + j0 + jl;
            h_out[hoff] = hn;
            __nv_bfloat16 hh;
            __nv_bfloat16 hl;
            split_bf16(hn, &hh, &hl);
            nhhi[hoff] = hh;
            nhlo[hoff] = hl;
            if (t == TT - 1) {
                out[(size_t)TT * BB * HH + hoff] = hn;
                out[(size_t)TT * BB * HH + BB * HH + hoff] = cn;
            }
        }

        // grid-wide barrier
        if (t < TT - 1) {
            __threadfence();
            __syncthreads();
            if (tid == 0) {
                unsigned target = rel_base + (unsigned)(t + 1);
                unsigned old = atomicAdd(&g_arrive, 1);
                if (old == NCTA - 1) {
                    g_arrive = 0;
                    __threadfence();
                    *(volatile unsigned*)&g_release = target;
                } else {
                    while ((int)(*(volatile unsigned*)&g_release - target) < 0) {}
                    __threadfence();
                }
            }
            __syncthreads();
        }
    }
}

extern "C" void kernel_launch(void* const* d_in, const int* in_sizes, int n_in,
                              void* d_out, int out_size)
{
    const float* x    = (const float*)d_in[0];
    const float* h0   = (const float*)d_in[1];
    const float* c0   = (const float*)d_in[2];
    const float* w_ih = (const float*)d_in[3];
    const float* b_ih = (const float*)d_in[4];
    const float* w_hh = (const float*)d_in[5];
    const float* b_hh = (const float*)d_in[6];
    float* out = (float*)d_out;
    (void)in_sizes; (void)n_in; (void)out_size;

    // Prep: bf16 hi/lo splits
    prep_x_kernel<<<(int)(((size_t)TT * BB * DD + 255) / 256), 256>>>(x);
    prep_wih_kernel<<<(GG * DD + 255) / 256, 256>>>(w_ih);
    prep_whh_kernel<<<(GG * HH + 255) / 256, 256>>>(w_hh);
    prep_h_kernel<<<(BB * HH + 255) / 256, 256>>>(h0);

    // Phase 1: input projection on tensor cores
    cudaFuncSetAttribute(gemm_gx_mma,
                         cudaFuncAttributeMaxDynamicSharedMemorySize, P1_SMEM);
    dim3 g1(GG / 128, (TT * BB) / 128);
    gemm_gx_mma<<<g1, 256, P1_SMEM>>>(b_ih, b_hh);

    // Phase 2: persistent tensor-core recurrence
    cudaFuncSetAttribute(lstm_mma_kernel,
                         cudaFuncAttributeMaxDynamicSharedMemorySize, R_SMEM);
    lstm_mma_kernel<<<NCTA, 256, R_SMEM>>>(c0, out);
}

// round 8
// speedup vs baseline: 2.1682x; 1.0083x over previous
#include <cuda_runtime.h>
#include <cuda_bf16.h>
#include <math.h>
#include <stdint.h>

#define TT 512
#define BB 64
#define DD 1024
#define HH 1024
#define GG 4096
#define NCTA 128

// ---------------------------------------------------------------------------
// Device scratch (allocation-free rules: __device__ globals)
// ---------------------------------------------------------------------------
static __device__ float g_gx[(size_t)TT * BB * GG];            // input gates (+biases)
static __device__ __nv_bfloat16 g_xhi[(size_t)TT * BB * DD];   // x split
static __device__ __nv_bfloat16 g_xlo[(size_t)TT * BB * DD];
static __device__ __nv_bfloat16 g_wihhi[GG * DD];              // w_ih split
static __device__ __nv_bfloat16 g_wihlo[GG * DD];
static __device__ __nv_bfloat16 g_whhhi[GG * HH];              // w_hh split, CTA-tiled rows
static __device__ __nv_bfloat16 g_whhlo[GG * HH];
static __device__ __nv_bfloat16 g_hhi[2][BB * HH];             // h split ping-pong
static __device__ __nv_bfloat16 g_hlo[2][BB * HH];
static __device__ unsigned g_arrive = 0;
static __device__ unsigned g_release = 0;

// ---------------------------------------------------------------------------
// Baseline-PTX tensor helpers (sm_80+: compile for plain sm_103)
// ---------------------------------------------------------------------------
__device__ __forceinline__ uint32_t smem_u32(const void* p) {
    uint32_t a;
    asm("{ .reg .u64 t; cvta.to.shared.u64 t, %1; cvt.u32.u64 %0, t; }"
        : "=r"(a) : "l"(p));
    return a;
}
__device__ __forceinline__ void cp16(uint32_t dst, const void* src) {
    asm volatile("cp.async.cg.shared.global [%0], [%1], 16;" :: "r"(dst), "l"(src) : "memory");
}
#define CP_COMMIT() asm volatile("cp.async.commit_group;" ::: "memory")
#define CP_WAIT0()  asm volatile("cp.async.wait_group 0;" ::: "memory")
#define CP_WAIT1()  asm volatile("cp.async.wait_group 1;" ::: "memory")

__device__ __forceinline__ void ldsm4(uint32_t addr, uint32_t* r) {
    asm volatile("ldmatrix.sync.aligned.m8n8.x4.shared.b16 {%0,%1,%2,%3}, [%4];"
                 : "=r"(r[0]), "=r"(r[1]), "=r"(r[2]), "=r"(r[3]) : "r"(addr));
}
__device__ __forceinline__ void mma16816(float* c, const uint32_t* a, const uint32_t* b) {
    asm volatile("mma.sync.aligned.m16n8k16.row.col.f32.bf16.bf16.f32 "
                 "{%0,%1,%2,%3}, {%4,%5,%6,%7}, {%8,%9}, {%0,%1,%2,%3};"
                 : "+f"(c[0]), "+f"(c[1]), "+f"(c[2]), "+f"(c[3])
                 : "r"(a[0]), "r"(a[1]), "r"(a[2]), "r"(a[3]), "r"(b[0]), "r"(b[1]));
}

// ---------------------------------------------------------------------------
// Prep kernels: fp32 -> bf16 hi/lo splits
// ---------------------------------------------------------------------------
__device__ __forceinline__ void split_bf16(float v, __nv_bfloat16* hi, __nv_bfloat16* lo) {
    __nv_bfloat16 h = __float2bfloat16(v);
    *hi = h;
    *lo = __float2bfloat16(v - __bfloat162float(h));
}
__global__ void prep_x_kernel(const float* __restrict__ x) {
    size_t idx = (size_t)blockIdx.x * blockDim.x + threadIdx.x;
    if (idx >= (size_t)TT * BB * DD) return;
    split_bf16(x[idx], &g_xhi[idx], &g_xlo[idx]);
}
__global__ void prep_wih_kernel(const float* __restrict__ w) {
    int idx = blockIdx.x * blockDim.x + threadIdx.x;
    if (idx >= GG * DD) return;
    split_bf16(w[idx], &g_wihhi[idx], &g_wihlo[idx]);
}
// w_hh reorder: CTA cta owns 32 rows r = g*8+jl  <->  in_row = g*1024 + cta*8 + jl
__global__ void prep_whh_kernel(const float* __restrict__ w) {
    int idx = blockIdx.x * blockDim.x + threadIdx.x;
    if (idx >= GG * HH) return;
    int orow = idx >> 10, k = idx & 1023;
    int cta = orow >> 5, r = orow & 31;
    int g = r >> 3, jl = r & 7;
    int in_row = (g << 10) + (cta << 3) + jl;
    split_bf16(w[(size_t)in_row * HH + k], &g_whhhi[idx], &g_whhlo[idx]);
}
__global__ void prep_h_kernel(const float* __restrict__ h0) {
    int idx = blockIdx.x * blockDim.x + threadIdx.x;
    if (idx >= BB * HH) return;
    split_bf16(h0[idx], &g_hhi[0][idx], &g_hlo[0][idx]);
}

// ---------------------------------------------------------------------------
// Phase 1: gates_x = x @ w_ih^T + b_ih + b_hh  via mma.sync, 3-term split.
// Tiles 128x128x32, cp.async double-buffered. Warp grid 4m x 2n (m32 x n64).
// ---------------------------------------------------------------------------
#define P1_STG 10240      // one stage of one array: 128*40*2
#define P1_AHI 0
#define P1_ALO 20480
#define P1_BHI 40960
#define P1_BLO 61440
#define P1_SMEM 81920

__global__ __launch_bounds__(256, 2) void gemm_gx_mma(
    const float* __restrict__ bih, const float* __restrict__ bhh)
{
    extern __shared__ __align__(16) char sm[];
    const uint32_t sb = smem_u32(sm);
    const int tid = threadIdx.x;
    const int wid = tid >> 5, l = tid & 31;
    const int bm = blockIdx.y * 128, bn = blockIdx.x * 128;
    const int wm = wid & 3, wn = wid >> 2;

    const int a_r = wm * 32 + (l & 7) + ((l >> 3) & 1) * 8;
    const int a_cb = ((l >> 4) & 1) * 8;
    const int b_r = wn * 64 + (l & 7) + ((l >> 4) & 1) * 8;
    const int b_cb = ((l >> 3) & 1) * 8;

    float acc[2][8][4];
#pragma unroll
    for (int i = 0; i < 2; i++)
#pragma unroll
        for (int j = 0; j < 8; j++)
#pragma unroll
            for (int q = 0; q < 4; q++) acc[i][j][q] = 0.f;

    const int crow = tid >> 2, cseg = tid & 3;
    auto load_stage = [&](int c, int st) {
        const uint32_t so = st * P1_STG;
        size_t koff = (size_t)c * 32 + cseg * 8;
#pragma unroll
        for (int i = 0; i < 2; i++) {
            int row = crow + i * 64;
            uint32_t sofs = (uint32_t)(row * 80 + cseg * 16);
            cp16(sb + P1_AHI + so + sofs, g_xhi + (size_t)(bm + row) * DD + koff);
            cp16(sb + P1_ALO + so + sofs, g_xlo + (size_t)(bm + row) * DD + koff);
            cp16(sb + P1_BHI + so + sofs, g_wihhi + (size_t)(bn + row) * DD + koff);
            cp16(sb + P1_BLO + so + sofs, g_wihlo + (size_t)(bn + row) * DD + koff);
        }
        CP_COMMIT();
    };

    load_stage(0, 0);

    for (int c = 0; c < 32; c++) {
        if (c < 31) load_stage(c + 1, (c + 1) & 1);
        if (c < 31) { CP_WAIT1(); } else { CP_WAIT0(); }
        __syncthreads();
        const uint32_t so = (c & 1) * P1_STG;
#pragma unroll
        for (int kb = 0; kb < 32; kb += 16) {
            uint32_t ahi[2][4], alo[2][4];
#pragma unroll
            for (int am = 0; am < 2; am++) {
                uint32_t aofs = (uint32_t)((a_r + am * 16) * 80 + (kb + a_cb) * 2);
                ldsm4(sb + P1_AHI + so + aofs, ahi[am]);
                ldsm4(sb + P1_ALO + so + aofs, alo[am]);
            }
#pragma unroll
            for (int bg = 0; bg < 4; bg++) {
                uint32_t bh[4], bl[4];
                uint32_t bofs = (uint32_t)((b_r + bg * 16) * 80 + (kb + b_cb) * 2);
                ldsm4(sb + P1_BHI + so + bofs, bh);
                ldsm4(sb + P1_BLO + so + bofs, bl);
#pragma unroll
                for (int am = 0; am < 2; am++)
#pragma unroll
                    for (int na = 0; na < 2; na++) {
                        float* cc = acc[am][bg * 2 + na];
                        mma16816(cc, ahi[am], bh + na * 2);
                        mma16816(cc, alo[am], bh + na * 2);
                        mma16816(cc, ahi[am], bl + na * 2);
                    }
            }
        }
        __syncthreads();
    }

#pragma unroll
    for (int am = 0; am < 2; am++) {
        int m0 = bm + wm * 32 + am * 16 + (l >> 2);
#pragma unroll
        for (int j = 0; j < 8; j++) {
            int n = bn + wn * 64 + j * 8 + 2 * (l & 3);
            float s0 = bih[n] + bhh[n];
            float s1 = bih[n + 1] + bhh[n + 1];
            float* c = acc[am][j];
            g_gx[(size_t)m0 * GG + n]           = c[0] + s0;
            g_gx[(size_t)m0 * GG + n + 1]       = c[1] + s1;
            g_gx[(size_t)(m0 + 8) * GG + n]     = c[2] + s0;
            g_gx[(size_t)(m0 + 8) * GG + n + 1] = c[3] + s1;
        }
    }
}

// ---------------------------------------------------------------------------
// Phase 2: persistent mma.sync recurrence. 128 CTAs x 512 threads (16 warps).
// CTA: D[64 batch x 32 gate-rows], K=1024 (8 chunks of 128), 3-term split.
// Warp pairs split each chunk's K (kh=0/1 -> 64 k each); partial D planes
// summed in the pointwise. W resident in SMEM; h streamed via cp.async.
// ---------------------------------------------------------------------------
#define R_SWHI 0            // 32 x 2064B = 66048
#define R_SWLO 66048
#define R_SH   132096       // 2 stages x 34816 (hi 17408 + lo 17408)
#define R_HSTG 34816
#define R_SMEM 201728
// sg (2 planes x 64 x 36 floats = 18432 B) aliases h-stage 0 (34816 B)

__global__ __launch_bounds__(512, 1) void lstm_mma_kernel(
    const float* __restrict__ c0, float* __restrict__ out)
{
    extern __shared__ __align__(16) char sm[];
    const uint32_t sb = smem_u32(sm);
    float* sg = (float*)(sm + R_SH);     // aliases stage 0 (safe: used post-mainloop)
    const int tid = threadIdx.x;
    const int wid = tid >> 5, l = tid & 31;
    const int j0 = blockIdx.x * 8;

    const unsigned rel_base = *(volatile unsigned*)&g_release;

    const __nv_bfloat16* whi = g_whhhi + (size_t)blockIdx.x * 32 * HH;
    const __nv_bfloat16* wlo = g_whhlo + (size_t)blockIdx.x * 32 * HH;

    // ---- Load W (hi+lo) into SMEM once ----
    for (int cid = tid; cid < 4096; cid += 512) {
        int row = cid >> 7, seg = cid & 127;
        uint32_t sofs = (uint32_t)(row * 2064 + seg * 16);
        *(uint4*)(sm + R_SWHI + sofs) = *(const uint4*)(whi + (size_t)row * HH + seg * 8);
        *(uint4*)(sm + R_SWLO + sofs) = *(const uint4*)(wlo + (size_t)row * HH + seg * 8);
    }

    // cell state: 1 elem/thread: b = tid>>3, jl = tid&7
    const int pb = tid >> 3, pjl = tid & 7;
    float c_reg = c0[(size_t)pb * HH + j0 + pjl];
    __syncthreads();

    // warp geometry: kh = K-half, w8 in 4m x 2n
    const int kh = wid >> 3, w8 = wid & 7;
    const int m0 = (w8 & 3) * 16, n0 = (w8 >> 2) * 16;
    const int a_r = m0 + (l & 7) + ((l >> 3) & 1) * 8;
    const int a_cb = ((l >> 4) & 1) * 8;
    const int b_r = n0 + (l & 7) + ((l >> 4) & 1) * 8;
    const int b_cb = ((l >> 3) & 1) * 8;

    const int hrow = tid >> 3, hseg = tid & 7;   // 64 rows x 16 segs, 2 passes

    // initial gx prefetch (t = 0)
    float gpre[4];
    {
        const float* gr = g_gx + (size_t)pb * GG + j0 + pjl;
#pragma unroll
        for (int g = 0; g < 4; g++) gpre[g] = gr[g * HH];
    }

    for (int t = 0; t < TT; t++) {
        const __nv_bfloat16* hhi = g_hhi[t & 1];
        const __nv_bfloat16* hlo = g_hlo[t & 1];

        float acc[2][4];
#pragma unroll
        for (int na = 0; na < 2; na++)
#pragma unroll
            for (int q = 0; q < 4; q++) acc[na][q] = 0.f;

        auto load_h = [&](int c, int st) {
            const uint32_t so = R_SH + st * R_HSTG;
            const size_t base = (size_t)hrow * HH + c * 128;
#pragma unroll
            for (int i = 0; i < 2; i++) {
                int seg = hseg + i * 8;
                uint32_t sofs = (uint32_t)(hrow * 272 + seg * 16);
                cp16(sb + so + sofs,         hhi + base + seg * 8);
                cp16(sb + so + 17408 + sofs, hlo + base + seg * 8);
            }
            CP_COMMIT();
        };

        load_h(0, 0);
        for (int c = 0; c < 8; c++) {
            if (c < 7) load_h(c + 1, (c + 1) & 1);
            if (c < 7) { CP_WAIT1(); } else { CP_WAIT0(); }
            __syncthreads();
            const uint32_t so = R_SH + (c & 1) * R_HSTG;
#pragma unroll
            for (int kk = 0; kk < 64; kk += 16) {
                const int kb = kh * 64 + kk;
                uint32_t ahi[4], alo[4], bh[4], bl[4];
                uint32_t aofs = (uint32_t)(a_r * 272 + (kb + a_cb) * 2);
                ldsm4(sb + so + aofs, ahi);
                ldsm4(sb + so + 17408 + aofs, alo);
                uint32_t bofs = (uint32_t)(b_r * 2064 + (c * 128 + kb + b_cb) * 2);
                ldsm4(sb + R_SWHI + bofs, bh);
                ldsm4(sb + R_SWLO + bofs, bl);
#pragma unroll
                for (int na = 0; na < 2; na++) {
                    mma16816(acc[na], ahi, bh + na * 2);
                    mma16816(acc[na], alo, bh + na * 2);
                    mma16816(acc[na], ahi, bl + na * 2);
                }
            }
            __syncthreads();
        }

        // prefetch next step's gx now (hides DRAM latency under epilogue+barrier)
        float gnext[4];
        if (t < TT - 1) {
            const float* gr = g_gx + (size_t)(t + 1) * BB * GG
                              + (size_t)pb * GG + j0 + pjl;
#pragma unroll
            for (int g = 0; g < 4; g++) gnext[g] = gr[g * HH];
        }

        // stage partial D planes to SMEM: plane kh
        {
            float* sgp = sg + kh * (64 * 36);
            int m = m0 + (l >> 2);
#pragma unroll
            for (int na = 0; na < 2; na++) {
                int n = n0 + na * 8 + 2 * (l & 3);
                *(float2*)&sgp[m * 36 + n]       = make_float2(acc[na][0], acc[na][1]);
                *(float2*)&sgp[(m + 8) * 36 + n] = make_float2(acc[na][2], acc[na][3]);
            }
        }
        __syncthreads();

        // pointwise LSTM cell: 512 elems, 1/thread
        float* h_out = out + (size_t)t * BB * HH;
        __nv_bfloat16* nhhi = g_hhi[(t + 1) & 1];
        __nv_bfloat16* nhlo = g_hlo[(t + 1) & 1];
        {
            const float* s0 = sg + pb * 36;
            const float* s1 = sg + 64 * 36 + pb * 36;
            float gi = s0[pjl]      + s1[pjl]      + gpre[0];
            float gf = s0[8 + pjl]  + s1[8 + pjl]  + gpre[1];
            float gg = s0[16 + pjl] + s1[16 + pjl] + gpre[2];
            float go = s0[24 + pjl] + s1[24 + pjl] + gpre[3];
            float ig = 1.0f / (1.0f + __expf(-gi));
            float fg = 1.0f / (1.0f + __expf(-gf));
            float gv = tanhf(gg);
            float og = 1.0f / (1.0f + __expf(-go));
            float cn = fg * c_reg + ig * gv;
            float hn = og * tanhf(cn);
            c_reg = cn;
            size_t hoff = (size_t)pb * HH + j0 + pjl;
            h_out[hoff] = hn;
            __nv_bfloat16 hh, hl;
            split_bf16(hn, &hh, &hl);
            nhhi[hoff] = hh;
            nhlo[hoff] = hl;
            if (t == TT - 1) {
                out[(size_t)TT * BB * HH + hoff] = hn;
                out[(size_t)TT * BB * HH + BB * HH + hoff] = cn;
            }
        }
#pragma unroll
        for (int g = 0; g < 4; g++) gpre[g] = gnext[g];

        // grid-wide barrier
        if (t < TT - 1) {
            __threadfence();
            __syncthreads();
            if (tid == 0) {
                unsigned target = rel_base + (unsigned)(t + 1);
                unsigned old = atomicAdd(&g_arrive, 1);
                if (old == NCTA - 1) {
                    g_arrive = 0;
                    __threadfence();
                    *(volatile unsigned*)&g_release = target;
                }
            }
            // all warps: lane 0 spins, then warp-local sync (no extra CTA sync)
            {
                unsigned target = rel_base + (unsigned)(t + 1);
                if (l == 0) {
                    while ((int)(*(volatile unsigned*)&g_release - target) < 0) {}
                }
                __syncwarp();
                __threadfence();   // acquire: order subsequent h loads after release
            }
        }
    }
}

extern "C" void kernel_launch(void* const* d_in, const int* in_sizes, int n_in,
                              void* d_out, int out_size)
{
    const float* x    = (const float*)d_in[0];
    const float* h0   = (const float*)d_in[1];
    const float* c0   = (const float*)d_in[2];
    const float* w_ih = (const float*)d_in[3];
    const float* b_ih = (const float*)d_in[4];
    const float* w_hh = (const float*)d_in[5];
    const float* b_hh = (const float*)d_in[6];
    float* out = (float*)d_out;
    (void)in_sizes; (void)n_in; (void)out_size;

    // Prep: bf16 hi/lo splits
    prep_x_kernel<<<(int)(((size_t)TT * BB * DD + 255) / 256), 256>>>(x);
    prep_wih_kernel<<<(GG * DD + 255) / 256, 256>>>(w_ih);
    prep_whh_kernel<<<(GG * HH + 255) / 256, 256>>>(w_hh);
    prep_h_kernel<<<(BB * HH + 255) / 256, 256>>>(h0);

    // Phase 1: input projection on tensor cores
    cudaFuncSetAttribute(gemm_gx_mma,
                         cudaFuncAttributeMaxDynamicSharedMemorySize, P1_SMEM);
    dim3 g1(GG / 128, (TT * BB) / 128);
    gemm_gx_mma<<<g1, 256, P1_SMEM>>>(b_ih, b_hh);

    // Phase 2: persistent tensor-core recurrence
    cudaFuncSetAttribute(lstm_mma_kernel,
                         cudaFuncAttributeMaxDynamicSharedMemorySize, R_SMEM);
    lstm_mma_kernel<<<NCTA, 512, R_SMEM>>>(c0, out);
}